// round 8
// baseline (speedup 1.0000x reference)
#include <cuda_runtime.h>
#include <cstdint>

// Problem constants
#define Bc   4
#define Cc   256
#define Hc   64
#define Wc   64
#define OCc  256
#define Kc   9
#define Pc   4096
#define CKc  (Cc*Kc)    // 2304

__device__ float g_cols[(size_t)Bc * CKc * Pc];
__device__ float g_wtf[(size_t)OCc * CKc];      // tf32-rounded weights

__device__ __forceinline__ uint32_t cvt_tf32(float f) {
    uint32_t r;
    asm("cvt.rna.tf32.f32 %0, %1;" : "=r"(r) : "f"(f));
    return r;
}

// ---------------------------------------------------------------------------
// Stage 0: round weights to tf32
// ---------------------------------------------------------------------------
__global__ __launch_bounds__(256) void round_weights(const float* __restrict__ w) {
    int i = blockIdx.x * 256 + threadIdx.x;
    if (i < OCc * CKc) g_wtf[i] = __uint_as_float(cvt_tf32(w[i]));
}

// ---------------------------------------------------------------------------
// Stage 1: deformable im2col — stores tf32-rounded values.
// ---------------------------------------------------------------------------
__global__ __launch_bounds__(256) void dcn_im2col(
    const float* __restrict__ x,
    const float* __restrict__ offset)
{
    int tid = blockIdx.x * 256 + threadIdx.x;
    int p = tid & (Pc - 1);
    int k = (tid >> 12) % Kc;
    int b = tid / (Pc * Kc);

    int ho = p >> 6;
    int wo = p & 63;
    int ki = k / 3;
    int kj = k - 3 * ki;

    const float* offb = offset + ((size_t)b * 18) * Pc;
    float dy = offb[(2 * k    ) * Pc + p];
    float dx = offb[(2 * k + 1) * Pc + p];

    float ph = (float)(ho - 1 + ki) + dy;
    float pw = (float)(wo - 1 + kj) + dx;

    float h0f = floorf(ph), w0f = floorf(pw);
    float lh = ph - h0f,    lw = pw - w0f;
    int h0 = (int)h0f, w0 = (int)w0f;
    int h1 = h0 + 1,   w1 = w0 + 1;

    float vh0 = (h0 >= 0 && h0 < Hc) ? 1.f : 0.f;
    float vh1 = (h1 >= 0 && h1 < Hc) ? 1.f : 0.f;
    float vw0 = (w0 >= 0 && w0 < Wc) ? 1.f : 0.f;
    float vw1 = (w1 >= 0 && w1 < Wc) ? 1.f : 0.f;

    float w00 = (1.f - lh) * (1.f - lw) * vh0 * vw0;
    float w01 = (1.f - lh) * lw         * vh0 * vw1;
    float w10 = lh * (1.f - lw)         * vh1 * vw0;
    float w11 = lh * lw                 * vh1 * vw1;

    int ih0 = min(max(h0, 0), Hc - 1);
    int ih1 = min(max(h1, 0), Hc - 1);
    int iw0 = min(max(w0, 0), Wc - 1);
    int iw1 = min(max(w1, 0), Wc - 1);

    int i00 = ih0 * Wc + iw0;
    int i01 = ih0 * Wc + iw1;
    int i10 = ih1 * Wc + iw0;
    int i11 = ih1 * Wc + iw1;

    const float* xb = x + (size_t)b * Cc * Pc;
    float* colp = g_cols + (size_t)b * CKc * Pc + (size_t)k * Pc + p;

#pragma unroll 4
    for (int c = 0; c < Cc; ++c) {
        const float* xc = xb + (size_t)c * Pc;
        float v = w00 * xc[i00] + w01 * xc[i01] + w10 * xc[i10] + w11 * xc[i11];
        colp[(size_t)c * (Kc * Pc)] = __uint_as_float(cvt_tf32(v));
    }
}

// ---------------------------------------------------------------------------
// Stage 2: tf32 mma.sync GEMM. BM=128, BN=128, BK=16, 256 threads, 2 CTAs/SM.
// A: 3-stage cp.async smem + ldmatrix. B: DIRECT LDG fragments from g_cols
// with half-tile register prefetch (no smem, no barrier dependency).
// ---------------------------------------------------------------------------
#define BM 128
#define BN 128
#define BK 16
#define NT (CKc / BK)      // 144
#define STAGES 3
#define ASTRB 80           // A smem row stride BYTES
#define ABYTES (BM * ASTRB)          // 10240
#define SM_TOTAL (STAGES * ABYTES)   // 30720

__device__ __forceinline__ uint32_t smem_u32(const void* p) {
    uint32_t a;
    asm("{ .reg .u64 t; cvta.to.shared.u64 t, %1; cvt.u32.u64 %0, t; }"
        : "=r"(a) : "l"(p));
    return a;
}
__device__ __forceinline__ void cp_async16(uint32_t dst, const void* src) {
    asm volatile("cp.async.cg.shared.global [%0], [%1], 16;"
                 :: "r"(dst), "l"(src) : "memory");
}
__device__ __forceinline__ void cp_commit() {
    asm volatile("cp.async.commit_group;" ::: "memory");
}
template <int N>
__device__ __forceinline__ void cp_wait() {
    asm volatile("cp.async.wait_group %0;" :: "n"(N) : "memory");
}
__device__ __forceinline__ void ldmx4(uint32_t addr, uint32_t r[4]) {
    asm volatile("ldmatrix.sync.aligned.m8n8.x4.shared.b16 {%0,%1,%2,%3}, [%4];"
                 : "=r"(r[0]), "=r"(r[1]), "=r"(r[2]), "=r"(r[3]) : "r"(addr));
}
__device__ __forceinline__ void mma_tf32(float c[4],
                                         uint32_t a0, uint32_t a1, uint32_t a2, uint32_t a3,
                                         uint32_t b0, uint32_t b1) {
    asm volatile(
        "mma.sync.aligned.m16n8k8.row.col.f32.tf32.tf32.f32 "
        "{%0,%1,%2,%3}, {%4,%5,%6,%7}, {%8,%9}, {%0,%1,%2,%3};"
        : "+f"(c[0]), "+f"(c[1]), "+f"(c[2]), "+f"(c[3])
        : "r"(a0), "r"(a1), "r"(a2), "r"(a3), "r"(b0), "r"(b1));
}

__global__ __launch_bounds__(256, 2) void dcn_gemm_mma(
    float* __restrict__ out)            // [B, OC, P]
{
    extern __shared__ float sm[];
    const uint32_t sbA = smem_u32(sm);                  // STAGES x ABYTES

    const int tid = threadIdx.x;
    const int wid = tid >> 5;          // 0..7
    const int lane = tid & 31;
    const int warp_m = wid >> 2;       // 0..1  -> M offset *64
    const int warp_n = wid & 3;        // 0..3  -> N offset *32
    const int r = lane >> 2;
    const int c4 = lane & 3;

    const int bx = blockIdx.x;         // N tile (0..31)
    const int by = blockIdx.y;         // M tile (0..1)
    const int b  = blockIdx.z;         // batch

    const float* Ag = g_wtf + (size_t)by * BM * CKc;
    // per-thread B fragment base: row (k=c4), col n = bx*128 + warp_n*32 + r
    const float* Bq = g_cols + (size_t)b * CKc * Pc
                    + (size_t)c4 * Pc + bx * BN + warp_n * 32 + r;

    float acc[4][4][4];
#pragma unroll
    for (int i = 0; i < 4; ++i)
#pragma unroll
        for (int j = 0; j < 4; ++j)
#pragma unroll
            for (int q = 0; q < 4; ++q) acc[i][j][q] = 0.f;

    // A staging: 512 float4 chunks, 2/thread
    auto issue_A = [&](int t) {
        const uint32_t abase = sbA + (t % STAGES) * ABYTES;
#pragma unroll
        for (int i = 0; i < 2; ++i) {
            int ch = tid + i * 256;
            int m = ch >> 2, k4 = ch & 3;
            cp_async16(abase + (uint32_t)(m * ASTRB + k4 * 16),
                       Ag + (size_t)m * CKc + t * BK + k4 * 4);
        }
    };
    // B half-tile fragment load: half index hk = t*2 + kk8  (k base = hk*8)
    auto load_B = [&](int hk, uint32_t bf[4][2]) {
        const float* bp = Bq + (size_t)hk * 8 * Pc;
#pragma unroll
        for (int ni = 0; ni < 4; ++ni) {
            bf[ni][0] = __float_as_uint(__ldg(bp + ni * 8));
            bf[ni][1] = __float_as_uint(__ldg(bp + (size_t)4 * Pc + ni * 8));
        }
    };

    // ---- prologue ----
#pragma unroll
    for (int s = 0; s < STAGES - 1; ++s) { issue_A(s); cp_commit(); }

    uint32_t bcur[4][2], bnxt[4][2];
    load_B(0, bcur);

    const uint32_t a_lane = (uint32_t)((warp_m * 64 + (lane & 15)) * ASTRB
                                       + ((lane & 16) ? 16 : 0));

    for (int t = 0; t < NT; ++t) {
        cp_wait<STAGES - 2>();
        __syncthreads();

        if (t + STAGES - 1 < NT) issue_A(t + STAGES - 1);
        cp_commit();

        const uint32_t abase = sbA + (t % STAGES) * ABYTES + a_lane;

        // ---- half kk8 = 0 ----
        load_B(t * 2 + 1, bnxt);                 // prefetch next half
        {
            uint32_t af[4][4];
#pragma unroll
            for (int mi = 0; mi < 4; ++mi)
                ldmx4(abase + (uint32_t)(mi * 16 * ASTRB), af[mi]);
#pragma unroll
            for (int mi = 0; mi < 4; ++mi)
#pragma unroll
                for (int ni = 0; ni < 4; ++ni)
                    mma_tf32(acc[mi][ni], af[mi][0], af[mi][1], af[mi][2], af[mi][3],
                             bcur[ni][0], bcur[ni][1]);
        }

        // ---- half kk8 = 1 ----
        if (t + 1 < NT) load_B(t * 2 + 2, bcur); // prefetch first half of next tile
        {
            uint32_t af[4][4];
#pragma unroll
            for (int mi = 0; mi < 4; ++mi)
                ldmx4(abase + (uint32_t)(mi * 16 * ASTRB + 32), af[mi]);
#pragma unroll
            for (int mi = 0; mi < 4; ++mi)
#pragma unroll
                for (int ni = 0; ni < 4; ++ni)
                    mma_tf32(acc[mi][ni], af[mi][0], af[mi][1], af[mi][2], af[mi][3],
                             bnxt[ni][0], bnxt[ni][1]);
        }
    }

    // ---- epilogue: direct STG from fragments ----
    float* outb = out + ((size_t)b * OCc + by * BM) * Pc + (size_t)bx * BN;
#pragma unroll
    for (int mi = 0; mi < 4; ++mi) {
        int oc0 = warp_m * 64 + mi * 16 + r;
#pragma unroll
        for (int ni = 0; ni < 4; ++ni) {
            int p = warp_n * 32 + ni * 8 + 2 * c4;
            float2 v0 = make_float2(acc[mi][ni][0], acc[mi][ni][1]);
            float2 v1 = make_float2(acc[mi][ni][2], acc[mi][ni][3]);
            *(float2*)(outb + (size_t) oc0      * Pc + p) = v0;
            *(float2*)(outb + (size_t)(oc0 + 8) * Pc + p) = v1;
        }
    }
}

// ---------------------------------------------------------------------------
extern "C" void kernel_launch(void* const* d_in, const int* in_sizes, int n_in,
                              void* d_out, int out_size) {
    const float* x      = (const float*)d_in[0];
    const float* offset = (const float*)d_in[1];
    const float* weight = (const float*)d_in[2];
    float* out = (float*)d_out;

    cudaFuncSetAttribute(dcn_gemm_mma,
                         cudaFuncAttributeMaxDynamicSharedMemorySize, SM_TOTAL);

    round_weights<<<(OCc * CKc + 255) / 256, 256>>>(weight);
    dcn_im2col<<<(Bc * Kc * Pc) / 256, 256>>>(x, offset);

    dim3 grid(Pc / BN, OCc / BM, Bc);   // (32, 2, 4) = 256 CTAs, 2 per SM
    dcn_gemm_mma<<<grid, 256, SM_TOTAL>>>(out);
}

// round 9
// speedup vs baseline: 1.1721x; 1.1721x over previous
#include <cuda_runtime.h>
#include <cstdint>

// Problem constants
#define Bc   4
#define Cc   256
#define Hc   64
#define Wc   64
#define OCc  256
#define Kc   9
#define Pc   4096
#define CKc  (Cc*Kc)    // 2304

__device__ float g_cols[(size_t)Bc * CKc * Pc];
__device__ float g_wtf[(size_t)OCc * CKc];      // tf32-rounded weights

__device__ __forceinline__ uint32_t cvt_tf32(float f) {
    uint32_t r;
    asm("cvt.rna.tf32.f32 %0, %1;" : "=r"(r) : "f"(f));
    return r;
}

// ---------------------------------------------------------------------------
// Stage 0+1 merged: blocks [0,576) do deformable im2col; blocks [576,2880)
// round weights to tf32. One launch instead of two.
// ---------------------------------------------------------------------------
#define IM2COL_BLOCKS 576              // B*K*P / 256
#define RW_BLOCKS     ((OCc * CKc) / 256)   // 2304

__global__ __launch_bounds__(256) void dcn_stage01(
    const float* __restrict__ x,
    const float* __restrict__ offset,
    const float* __restrict__ w)
{
    if (blockIdx.x >= IM2COL_BLOCKS) {
        int i = (blockIdx.x - IM2COL_BLOCKS) * 256 + threadIdx.x;
        g_wtf[i] = __uint_as_float(cvt_tf32(w[i]));
        return;
    }

    int tid = blockIdx.x * 256 + threadIdx.x;
    int p = tid & (Pc - 1);
    int k = (tid >> 12) % Kc;
    int b = tid / (Pc * Kc);

    int ho = p >> 6;
    int wo = p & 63;
    int ki = k / 3;
    int kj = k - 3 * ki;

    const float* offb = offset + ((size_t)b * 18) * Pc;
    float dy = offb[(2 * k    ) * Pc + p];
    float dx = offb[(2 * k + 1) * Pc + p];

    float ph = (float)(ho - 1 + ki) + dy;
    float pw = (float)(wo - 1 + kj) + dx;

    float h0f = floorf(ph), w0f = floorf(pw);
    float lh = ph - h0f,    lw = pw - w0f;
    int h0 = (int)h0f, w0 = (int)w0f;
    int h1 = h0 + 1,   w1 = w0 + 1;

    float vh0 = (h0 >= 0 && h0 < Hc) ? 1.f : 0.f;
    float vh1 = (h1 >= 0 && h1 < Hc) ? 1.f : 0.f;
    float vw0 = (w0 >= 0 && w0 < Wc) ? 1.f : 0.f;
    float vw1 = (w1 >= 0 && w1 < Wc) ? 1.f : 0.f;

    float w00 = (1.f - lh) * (1.f - lw) * vh0 * vw0;
    float w01 = (1.f - lh) * lw         * vh0 * vw1;
    float w10 = lh * (1.f - lw)         * vh1 * vw0;
    float w11 = lh * lw                 * vh1 * vw1;

    int ih0 = min(max(h0, 0), Hc - 1);
    int ih1 = min(max(h1, 0), Hc - 1);
    int iw0 = min(max(w0, 0), Wc - 1);
    int iw1 = min(max(w1, 0), Wc - 1);

    int i00 = ih0 * Wc + iw0;
    int i01 = ih0 * Wc + iw1;
    int i10 = ih1 * Wc + iw0;
    int i11 = ih1 * Wc + iw1;

    const float* xb = x + (size_t)b * Cc * Pc;
    float* colp = g_cols + (size_t)b * CKc * Pc + (size_t)k * Pc + p;

#pragma unroll 4
    for (int c = 0; c < Cc; ++c) {
        const float* xc = xb + (size_t)c * Pc;
        float v = w00 * xc[i00] + w01 * xc[i01] + w10 * xc[i10] + w11 * xc[i11];
        colp[(size_t)c * (Kc * Pc)] = __uint_as_float(cvt_tf32(v));
    }
}

// ---------------------------------------------------------------------------
// Stage 2: tf32 mma.sync GEMM. BM=128, BN=128, BK=32, 3 stages, 256 threads,
// 2 CTAs/SM.  Warp grid 2(m) x 4(n), warp tile 64x32.  B-fragment LDS is
// software-pipelined across k8 chunks.
// ---------------------------------------------------------------------------
#define BM 128
#define BN 128
#define BK 32
#define NT (CKc / BK)      // 72
#define STAGES 3
#define ASTRB 144          // A smem row stride BYTES (36 words): ldmatrix conflict-free
#define ABYTES (BM * ASTRB)          // 18432
#define BSTR 136           // B smem row stride (words)
#define BBYTES (BK * BSTR * 4)       // 17408
#define SM_TOTAL (STAGES * (ABYTES + BBYTES))   // 107520

__device__ __forceinline__ uint32_t smem_u32(const void* p) {
    uint32_t a;
    asm("{ .reg .u64 t; cvta.to.shared.u64 t, %1; cvt.u32.u64 %0, t; }"
        : "=r"(a) : "l"(p));
    return a;
}
__device__ __forceinline__ void cp_async16(uint32_t dst, const void* src) {
    asm volatile("cp.async.cg.shared.global [%0], [%1], 16;"
                 :: "r"(dst), "l"(src) : "memory");
}
__device__ __forceinline__ void cp_commit() {
    asm volatile("cp.async.commit_group;" ::: "memory");
}
template <int N>
__device__ __forceinline__ void cp_wait() {
    asm volatile("cp.async.wait_group %0;" :: "n"(N) : "memory");
}
__device__ __forceinline__ void ldmx4(uint32_t addr, uint32_t r[4]) {
    asm volatile("ldmatrix.sync.aligned.m8n8.x4.shared.b16 {%0,%1,%2,%3}, [%4];"
                 : "=r"(r[0]), "=r"(r[1]), "=r"(r[2]), "=r"(r[3]) : "r"(addr));
}
__device__ __forceinline__ void mma_tf32(float c[4],
                                         uint32_t a0, uint32_t a1, uint32_t a2, uint32_t a3,
                                         uint32_t b0, uint32_t b1) {
    asm volatile(
        "mma.sync.aligned.m16n8k8.row.col.f32.tf32.tf32.f32 "
        "{%0,%1,%2,%3}, {%4,%5,%6,%7}, {%8,%9}, {%0,%1,%2,%3};"
        : "+f"(c[0]), "+f"(c[1]), "+f"(c[2]), "+f"(c[3])
        : "r"(a0), "r"(a1), "r"(a2), "r"(a3), "r"(b0), "r"(b1));
}

__global__ __launch_bounds__(256, 2) void dcn_gemm_mma(
    float* __restrict__ out)            // [B, OC, P]
{
    extern __shared__ float sm[];
    const uint32_t sbA = smem_u32(sm);                  // STAGES x ABYTES
    const uint32_t sbB = sbA + STAGES * ABYTES;
    float* Bs = sm + (STAGES * ABYTES) / 4;

    const int tid = threadIdx.x;
    const int wid = tid >> 5;          // 0..7
    const int lane = tid & 31;
    const int warp_m = wid >> 2;       // 0..1  -> M offset *64
    const int warp_n = wid & 3;        // 0..3  -> N offset *32
    const int r = lane >> 2;
    const int c4 = lane & 3;

    const int bx = blockIdx.x;         // N tile (0..31)
    const int by = blockIdx.y;         // M tile (0..1)
    const int b  = blockIdx.z;         // batch

    const float* Ag = g_wtf + (size_t)by * BM * CKc;
    const float* Bg = g_cols + (size_t)b * CKc * Pc + (size_t)bx * BN;

    float acc[4][4][4];
#pragma unroll
    for (int i = 0; i < 4; ++i)
#pragma unroll
        for (int j = 0; j < 4; ++j)
#pragma unroll
            for (int q = 0; q < 4; ++q) acc[i][j][q] = 0.f;

    // Staging per tile: A = 1024 float4 (4/thread), B = 1024 float4 (4/thread)
    auto issue_tile = [&](int t) {
        const int buf = t % STAGES;
        const uint32_t abase = sbA + buf * ABYTES;
        const uint32_t bbase = sbB + buf * BBYTES;
#pragma unroll
        for (int i = 0; i < 4; ++i) {
            int ch = tid + i * 256;
            int m = ch >> 3, k4 = ch & 7;
            cp_async16(abase + (uint32_t)(m * ASTRB + k4 * 16),
                       Ag + (size_t)m * CKc + t * BK + k4 * 4);
        }
#pragma unroll
        for (int j = 0; j < 4; ++j) {
            int ch = tid + j * 256;
            int k = ch >> 5, n16 = ch & 31;
            cp_async16(bbase + (uint32_t)(k * (BSTR * 4) + n16 * 16),
                       Bg + (size_t)(t * BK + k) * Pc + n16 * 4);
        }
    };

    // ---- prologue: stages 0,1 ----
#pragma unroll
    for (int s = 0; s < STAGES - 1; ++s) { issue_tile(s); cp_commit(); }

    const uint32_t a_lane = (uint32_t)((warp_m * 64 + (lane & 15)) * ASTRB
                                       + ((lane & 16) ? 16 : 0));

    for (int t = 0; t < NT; ++t) {
        const int buf = t % STAGES;
        cp_wait<STAGES - 2>();
        __syncthreads();

        if (t + STAGES - 1 < NT) issue_tile(t + STAGES - 1);
        cp_commit();   // always commit -> wait_group counting stays exact

        const uint32_t abase = sbA + buf * ABYTES + a_lane;
        const float* Bp = Bs + buf * (BBYTES / 4) + warp_n * 32;

        // B fragments pipelined one k8-chunk ahead
        uint32_t bcur[4][2], bnxt[4][2];
#pragma unroll
        for (int ni = 0; ni < 4; ++ni) {
            int n = ni * 8 + r;
            bcur[ni][0] = __float_as_uint(Bp[(c4    ) * BSTR + n]);
            bcur[ni][1] = __float_as_uint(Bp[(c4 + 4) * BSTR + n]);
        }

#pragma unroll
        for (int kc = 0; kc < 4; ++kc) {
            uint32_t af[4][4];
#pragma unroll
            for (int mi = 0; mi < 4; ++mi)
                ldmx4(abase + (uint32_t)(mi * 16 * ASTRB + kc * 32), af[mi]);

            if (kc < 3) {
                const int kk = (kc + 1) * 8;
#pragma unroll
                for (int ni = 0; ni < 4; ++ni) {
                    int n = ni * 8 + r;
                    bnxt[ni][0] = __float_as_uint(Bp[(kk + c4    ) * BSTR + n]);
                    bnxt[ni][1] = __float_as_uint(Bp[(kk + c4 + 4) * BSTR + n]);
                }
            }

#pragma unroll
            for (int mi = 0; mi < 4; ++mi)
#pragma unroll
                for (int ni = 0; ni < 4; ++ni)
                    mma_tf32(acc[mi][ni], af[mi][0], af[mi][1], af[mi][2], af[mi][3],
                             bcur[ni][0], bcur[ni][1]);

#pragma unroll
            for (int ni = 0; ni < 4; ++ni) {
                bcur[ni][0] = bnxt[ni][0];
                bcur[ni][1] = bnxt[ni][1];
            }
        }
    }

    // ---- epilogue: direct STG from fragments ----
    float* outb = out + ((size_t)b * OCc + by * BM) * Pc + (size_t)bx * BN;
#pragma unroll
    for (int mi = 0; mi < 4; ++mi) {
        int oc0 = warp_m * 64 + mi * 16 + r;
#pragma unroll
        for (int ni = 0; ni < 4; ++ni) {
            int p = warp_n * 32 + ni * 8 + 2 * c4;
            float2 v0 = make_float2(acc[mi][ni][0], acc[mi][ni][1]);
            float2 v1 = make_float2(acc[mi][ni][2], acc[mi][ni][3]);
            *(float2*)(outb + (size_t) oc0      * Pc + p) = v0;
            *(float2*)(outb + (size_t)(oc0 + 8) * Pc + p) = v1;
        }
    }
}

// ---------------------------------------------------------------------------
extern "C" void kernel_launch(void* const* d_in, const int* in_sizes, int n_in,
                              void* d_out, int out_size) {
    const float* x      = (const float*)d_in[0];
    const float* offset = (const float*)d_in[1];
    const float* weight = (const float*)d_in[2];
    float* out = (float*)d_out;

    cudaFuncSetAttribute(dcn_gemm_mma,
                         cudaFuncAttributeMaxDynamicSharedMemorySize, SM_TOTAL);

    dcn_stage01<<<IM2COL_BLOCKS + RW_BLOCKS, 256>>>(x, offset, weight);

    dim3 grid(Pc / BN, OCc / BM, Bc);   // (32, 2, 4) = 256 CTAs, 2 per SM
    dcn_gemm_mma<<<grid, 256, SM_TOTAL>>>(out);
}